// round 7
// baseline (speedup 1.0000x reference)
#include <cuda_runtime.h>
#include <cstdint>
#include <math.h>

// RoI-Align FPN extractor, R7: pipeline + all channel-invariant address math
// hoisted to registers (staging offsets and the 16 tap offsets per bin).
// feats lvl i: (2, 256, 200>>i, 336>>i) fp32, stride 4<<i.
// rois: (512,5). out: (512, 256, 7, 7) fp32.

static constexpr int NS     = 14;
static constexpr int NCH    = 256;
static constexpr int BUFN   = 1216;   // per-channel staging floats (worst ~1179)
static constexpr int CPS    = 4;      // channels per stage
static constexpr int NSTAGE = 16;     // 64 / CPS
static constexpr int BINPAD = 52;
static constexpr int MAXSLOT= 5;      // ceil(BUFN/256)

__device__ __forceinline__ void cp_async4(uint32_t dst_smem, const float* src)
{
    asm volatile("cp.async.ca.shared.global [%0], [%1], 4;\n"
                 :: "r"(dst_smem), "l"(src));
}
__device__ __forceinline__ void cp_commit()
{
    asm volatile("cp.async.commit_group;\n");
}
__device__ __forceinline__ void cp_wait1()
{
    asm volatile("cp.async.wait_group 1;\n" ::: "memory");
}
__device__ __forceinline__ void cp_wait0()
{
    asm volatile("cp.async.wait_group 0;\n" ::: "memory");
}

__global__ void __launch_bounds__(256, 5)
roi_align_fpn_kernel(const float* __restrict__ f0, const float* __restrict__ f1,
                     const float* __restrict__ f2, const float* __restrict__ f3,
                     const float* __restrict__ rois, float* __restrict__ out)
{
    __shared__ float s_wy0[NS], s_wy1[NS], s_wx0[NS], s_wx1[NS];
    __shared__ int   s_iy0[NS], s_iy1[NS], s_ix0[NS], s_ix1[NS];
    __shared__ int   s_lvl, s_b;
    __shared__ float2 s_cy[4][BINPAD];
    __shared__ float2 s_cx[4][BINPAD];
    __shared__ float  s_buf[2][CPS][BUFN];

    const int n     = blockIdx.x >> 2;
    const int slice = blockIdx.x & 3;
    const int tid   = threadIdx.x;

    if (tid == 0) {
        const float* r = rois + (size_t)n * 5;
        float rb = r[0], rx1 = r[1], ry1 = r[2], rx2 = r[3], ry2 = r[4];
        float sc = sqrtf((rx2 - rx1) * (ry2 - ry1));
        int lvl = (int)floor(log2((double)sc / 56.0 + 1e-6));
        lvl = lvl < 0 ? 0 : (lvl > 3 ? 3 : lvl);
        s_lvl = lvl;
        s_b   = (int)rb;
        const int H = 200 >> lvl, W = 336 >> lvl;
        const float isc = 1.0f / (float)(4 << lvl);
        float x1 = rx1 * isc - 0.5f, y1 = ry1 * isc - 0.5f;
        float x2 = rx2 * isc - 0.5f, y2 = ry2 * isc - 0.5f;
        float bw = (x2 - x1) / 7.0f, bh = (y2 - y1) / 7.0f;
#pragma unroll 1
        for (int i = 0; i < NS; i++) {
            float off = (float)(i >> 1) + ((float)(i & 1) + 0.5f) * 0.5f;
            {
                float c  = x1 + off * bw;
                float v  = (c >= -1.0f && c <= (float)W) ? 1.0f : 0.0f;
                float cc = fminf(fmaxf(c, 0.0f), (float)W - 1.0f);
                int lo   = (int)floorf(cc);
                int hi   = min(lo + 1, W - 1);
                float fr = cc - (float)lo;
                s_ix0[i] = lo; s_ix1[i] = hi;
                s_wx0[i] = v * (1.0f - fr); s_wx1[i] = v * fr;
            }
            {
                float c  = y1 + off * bh;
                float v  = (c >= -1.0f && c <= (float)H) ? 1.0f : 0.0f;
                float cc = fminf(fmaxf(c, 0.0f), (float)H - 1.0f);
                int lo   = (int)floorf(cc);
                int hi   = min(lo + 1, H - 1);
                float fr = cc - (float)lo;
                s_iy0[i] = lo; s_iy1[i] = hi;
                s_wy0[i] = v * (1.0f - fr); s_wy1[i] = v * fr;
            }
        }
    }
    __syncthreads();

    const int lvl = s_lvl, b = s_b;
    const int H = 200 >> lvl, W = 336 >> lvl;
    const int HW = H * W;
    const float* fb = (lvl == 0) ? f0 : (lvl == 1) ? f1 : (lvl == 2) ? f2 : f3;
    fb += ((size_t)b * NCH + slice * 64) * HW;

    const int ymin  = s_iy0[0];
    const int xmin  = s_ix0[0];
    const int rowsN = s_iy1[NS - 1] - ymin + 1;
    const int colsN = s_ix1[NS - 1] - xmin + 1;
    const int colsPad = colsN | 1;
    const bool useSmem = (rowsN * colsPad) <= BUFN;

    const int stride = useSmem ? colsPad : W;
    const int oy0    = useSmem ? ymin : 0;
    const int ox0    = useSmem ? xmin : 0;

    if (tid < 196) {
        const int i   = tid / 49;
        const int bin = tid - i * 49;
        const int by  = bin / 7, bx = bin - by * 7;
        const int r   = 2 * by + (i >> 1);
        const int c   = 2 * bx + (i >> 1);
        int   iy = (i & 1) ? s_iy1[r] : s_iy0[r];
        float wy = (i & 1) ? s_wy1[r] : s_wy0[r];
        int   ix = (i & 1) ? s_ix1[c] : s_ix0[c];
        float wx = (i & 1) ? s_wx1[c] : s_wx0[c];
        s_cy[i][bin] = make_float2(__int_as_float((iy - oy0) * stride), wy);
        s_cx[i][bin] = make_float2(__int_as_float(ix - ox0), wx);
    }
    __syncthreads();

    // ---- channel-invariant compute coefficients (registers) ----
    const bool compute = tid < 196;
    const int  myBin   = compute ? (tid % 49) : 0;
    const int  myCh    = compute ? (tid / 49) : 0;
    int   idx16[16];          // flattened tap offsets offY[i]+offX[j]
    float wY[4], wX[4];
#pragma unroll
    for (int i = 0; i < 4; i++) {
        float2 cy = s_cy[i][myBin];
        float2 cx = s_cx[i][myBin];
        wY[i] = cy.y;
        wX[i] = cx.y;
        idx16[i * 4 + 0] = __float_as_int(cy.x);   // temp: offY
        idx16[i * 4 + 1] = __float_as_int(cx.x);   // temp: offX
    }
    {
        int offY[4] = { idx16[0], idx16[4], idx16[8],  idx16[12] };
        int offX[4] = { idx16[1], idx16[5], idx16[9],  idx16[13] };
#pragma unroll
        for (int i = 0; i < 4; i++)
#pragma unroll
            for (int j = 0; j < 4; j++)
                idx16[i * 4 + j] = offY[i] + offX[j];
    }

    float* oBase = out + ((size_t)n * NCH + slice * 64) * 49;

    if (useSmem) {
        // ---- channel-invariant staging offsets (registers, computed once) ----
        const unsigned umagic = 0xFFFFFFFFu / (unsigned)colsN + 1u;
        const int stageTot = rowsN * colsN;
        int srcOff[MAXSLOT], dstOff[MAXSLOT];
        int nSlots = 0;
#pragma unroll
        for (int k = 0; k < MAXSLOT; k++) {
            int i = tid + k * 256;
            if (i < stageTot) {
                unsigned r = (unsigned)(((unsigned long long)i * umagic) >> 32);
                int x = i - (int)r * colsN;
                srcOff[k] = (ymin + (int)r) * W + xmin + x;
                dstOff[k] = 4 * ((int)r * colsPad + x);
                nSlots = k + 1;
            }
        }

        const uint32_t smbase =
            (uint32_t)__cvta_generic_to_shared(&s_buf[0][0][0]);

        auto stage = [&](int s) {
            const float*  srcB = fb + (size_t)(s * CPS) * HW;
            uint32_t      dstB = smbase + (uint32_t)((s & 1) * CPS * BUFN) * 4u;
#pragma unroll
            for (int c = 0; c < CPS; c++) {
#pragma unroll
                for (int k = 0; k < MAXSLOT; k++) {
                    if (k < nSlots)
                        cp_async4(dstB + dstOff[k], srcB + srcOff[k]);
                }
                srcB += HW;
                dstB += BUFN * 4u;
            }
            cp_commit();
        };

        const float* b0 = &s_buf[0][myCh][0];
        const float* b1 = &s_buf[1][myCh][0];

        stage(0);
        stage(1);

#pragma unroll 1
        for (int ss = 0; ss < NSTAGE; ss += 2) {
#pragma unroll
            for (int half = 0; half < 2; half++) {
                const int s = ss + half;
                if (s == NSTAGE - 1) cp_wait0(); else cp_wait1();
                __syncthreads();
                if (compute) {
                    const float* base = half ? b1 : b0;   // compile-time per instance
                    float acc = 0.0f;
#pragma unroll
                    for (int i = 0; i < 4; i++) {
                        float ra = 0.0f;
#pragma unroll
                        for (int j = 0; j < 4; j++)
                            ra = fmaf(wX[j], base[idx16[i * 4 + j]], ra);
                        acc = fmaf(wY[i], ra, acc);
                    }
                    oBase[(size_t)s * (CPS * 49) + tid] = 0.25f * acc;
                }
                __syncthreads();
                if (s + 2 < NSTAGE) stage(s + 2);
            }
        }
    } else {
        // rare fallback: region exceeds buffer -> direct gmem gathers
#pragma unroll 1
        for (int s = 0; s < NSTAGE; s++) {
            if (compute) {
                const float* src = fb + (size_t)(s * CPS + myCh) * HW;
                float acc = 0.0f;
#pragma unroll
                for (int i = 0; i < 4; i++) {
                    float ra = 0.0f;
#pragma unroll
                    for (int j = 0; j < 4; j++)
                        ra = fmaf(wX[j], __ldg(src + idx16[i * 4 + j]), ra);
                    acc = fmaf(wY[i], ra, acc);
                }
                oBase[(size_t)s * (CPS * 49) + tid] = 0.25f * acc;
            }
        }
    }
}

extern "C" void kernel_launch(void* const* d_in, const int* in_sizes, int n_in,
                              void* d_out, int out_size)
{
    const float* f0   = (const float*)d_in[0];
    const float* f1   = (const float*)d_in[1];
    const float* f2   = (const float*)d_in[2];
    const float* f3   = (const float*)d_in[3];
    const float* rois = (const float*)d_in[4];
    float* out = (float*)d_out;

    const int nroi = in_sizes[4] / 5;   // 512
    roi_align_fpn_kernel<<<nroi * 4, 256>>>(f0, f1, f2, f3, rois, out);
}